// round 14
// baseline (speedup 1.0000x reference)
#include <cuda_runtime.h>
#include <math.h>

#define N_NODES 8192
#define SEQ 256
#define H 32
#define NPB 16
#define NE 262144
#define THREADS 64

typedef unsigned long long ull;

__device__ float g_h2[N_NODES * H];
__device__ float g_hW[N_NODES * H];
__device__ float g_agg[N_NODES * H];
__device__ float g_dinv[N_NODES];

__device__ __forceinline__ void ffma2(ull& d, ull a, ull b) {
    asm("fma.rn.f32x2 %0, %1, %2, %0;" : "+l"(d) : "l"(a), "l"(b));
}
__device__ __forceinline__ void fadd2(ull& d, ull a) {
    asm("add.rn.f32x2 %0, %0, %1;" : "+l"(d) : "l"(a));
}
__device__ __forceinline__ ull pack2(float lo, float hi) {
    ull r; asm("mov.b64 %0, {%1, %2};" : "=l"(r) : "f"(lo), "f"(hi)); return r;
}
__device__ __forceinline__ float2 unpack2(ull v) {
    float2 r; asm("mov.b64 {%0, %1}, %2;" : "=f"(r.x), "=f"(r.y) : "l"(v)); return r;
}
__device__ __forceinline__ float tanhap(float x) {
    float r; asm("tanh.approx.f32 %0, %1;" : "=f"(r) : "f"(x)); return r;
}
__device__ __forceinline__ float sigap(float x) {
    return fmaf(0.5f, tanhap(0.5f * x), 0.5f);
}

// dynamic smem layout (bytes)
#define OFF_WT 0
#define OFF_WH 16384
#define OFF_Z1 32768
#define OFF_Z2 40960
#define OFF_H1 49152
#define OFF_H2 51200
#define OFF_RM 53248
#define DYN_SMEM 53376

// =====================================================================
// Fused 2-layer LSTM, LN folded into LSTM2 matvec. 64 thr/block,
// thread owns z-rows j and j+64 (halves h-broadcast duplication).
// 16 nodes/block -> grid 512 -> ONE wave at 4 blocks/SM.
// Whh1 rows in regs; Wtil/Whh2 transposed-dense in shared.
// 2 barriers/step, skewed schedule (z2 lags one step).
// =====================================================================
__global__ void __launch_bounds__(THREADS, 4) lstm_kernel(
    const float* __restrict__ x,
    const float* __restrict__ Wih1, const float* __restrict__ Whh1,
    const float* __restrict__ bih1, const float* __restrict__ bhh1,
    const float* __restrict__ ln_g, const float* __restrict__ ln_b,
    const float* __restrict__ Wih2, const float* __restrict__ Whh2,
    const float* __restrict__ bih2, const float* __restrict__ bhh2)
{
    extern __shared__ __align__(16) char sm[];
    ulonglong2 (*wt2sh)[128] = (ulonglong2(*)[128])(sm + OFF_WT);
    ulonglong2 (*wh2sh)[128] = (ulonglong2(*)[128])(sm + OFF_WH);
    float (*z1s)[128] = (float(*)[128])(sm + OFF_Z1);
    float (*z2s)[128] = (float(*)[128])(sm + OFF_Z2);
    float (*h1s)[H]   = (float(*)[H])(sm + OFF_H1);
    float (*h2s)[H]   = (float(*)[H])(sm + OFF_H2);
    float2* rm        = (float2*)(sm + OFF_RM);

    const int tid  = threadIdx.x;
    const int j    = tid;          // row A (gates 0/1: sigmoid)
    const int j2   = tid + 64;     // row B (gates 2/3)
    const int base = blockIdx.x * NPB;

    // ---- stage Wtil/Whh2 (transposed-dense) + row constants ----
    float stilA = 0.f, qA = 0.f, stilB = 0.f, qB = 0.f;
    for (int r = tid; r < 128; r += 64) {
        float st = 0.f, q = 0.f;
#pragma unroll
        for (int k2 = 0; k2 < H / 2; k2++) {
            int k = 2 * k2;
            float wa = Wih2[r * H + k]     * ln_g[k];
            float wb = Wih2[r * H + k + 1] * ln_g[k + 1];
            ull wt = pack2(wa, wb);
            ull wh = pack2(Whh2[r * H + k], Whh2[r * H + k + 1]);
            if (k2 & 1) { wt2sh[k2 >> 1][r].y = wt; wh2sh[k2 >> 1][r].y = wh; }
            else        { wt2sh[k2 >> 1][r].x = wt; wh2sh[k2 >> 1][r].x = wh; }
            st += wa + wb;
            q  += Wih2[r * H + k] * ln_b[k] + Wih2[r * H + k + 1] * ln_b[k + 1];
        }
        q += bih2[r] + bhh2[r];
        if (r == j) { stilA = st; qA = q; } else { stilB = st; qB = q; }
    }
    // Whh1 rows in registers
    ull w1pA[H / 2], w1pB[H / 2];
#pragma unroll
    for (int k2 = 0; k2 < H / 2; k2++) {
        w1pA[k2] = pack2(Whh1[j * H + 2 * k2],  Whh1[j * H + 2 * k2 + 1]);
        w1pB[k2] = pack2(Whh1[j2 * H + 2 * k2], Whh1[j2 * H + 2 * k2 + 1]);
    }
    const float b1A = bih1[j] + bhh1[j],   wxA = Wih1[j];
    const float b1B = bih1[j2] + bhh1[j2], wxB = Wih1[j2];
    // row B activation: gate 2 (tanh) if j<32 else gate 3 (sigmoid)
    const float mSB = (j < 32) ? 1.0f : 0.5f;
    const float mAB = (j < 32) ? 1.0f : 0.5f;
    const float mBB = (j < 32) ? 0.0f : 0.5f;

    // phase2 ownership: unit u = lane, nodes {w, w+2, ..., w+14}
    const int w = tid >> 5;
    const int u = tid & 31;
    for (int i = tid; i < NPB * H; i += 64) {
        ((float*)h1s)[i] = 0.f;
        ((float*)h2s)[i] = 0.f;
    }
    float c1[8], c2[8];
#pragma unroll
    for (int n = 0; n < 8; n++) { c1[n] = 0.f; c2[n] = 0.f; }
    __syncthreads();

    for (int t = 0; t <= SEQ; t++) {
        const int tx = (t < SEQ) ? t : SEQ - 1;
        // ================= Phase1: 4 passes x 4 nodes =================
#pragma unroll
        for (int p = 0; p < 4; p++) {
            ull a1[4], a2[4], a3[4], d1[4], d2[4], d3[4];
#pragma unroll
            for (int m4 = 0; m4 < 4; m4++) {
                float xv = __ldg(x + (base + 4 * p + m4) * SEQ + tx);
                a1[m4] = pack2(fmaf(xv, wxA, b1A), 0.f);
                d1[m4] = pack2(fmaf(xv, wxB, b1B), 0.f);
                a2[m4] = 0ULL; a3[m4] = 0ULL; d2[m4] = 0ULL; d3[m4] = 0ULL;
            }
#pragma unroll
            for (int k4 = 0; k4 < H / 4; k4++) {
                ulonglong2 wtA = wt2sh[k4][j],  whA = wh2sh[k4][j];
                ulonglong2 wtB = wt2sh[k4][j2], whB = wh2sh[k4][j2];
                ull w1Ax = w1pA[2 * k4], w1Ay = w1pA[2 * k4 + 1];
                ull w1Bx = w1pB[2 * k4], w1By = w1pB[2 * k4 + 1];
#pragma unroll
                for (int m4 = 0; m4 < 4; m4++) {
                    int m = 4 * p + m4;
                    ulonglong2 h1v = *(const ulonglong2*)&h1s[m][k4 * 4];
                    ulonglong2 h2v = *(const ulonglong2*)&h2s[m][k4 * 4];
                    ffma2(a1[m4], w1Ax,  h1v.x); ffma2(a1[m4], w1Ay,  h1v.y);
                    ffma2(d1[m4], w1Bx,  h1v.x); ffma2(d1[m4], w1By,  h1v.y);
                    ffma2(a2[m4], wtA.x, h1v.x); ffma2(a2[m4], wtA.y, h1v.y);
                    ffma2(d2[m4], wtB.x, h1v.x); ffma2(d2[m4], wtB.y, h1v.y);
                    ffma2(a3[m4], whA.x, h2v.x); ffma2(a3[m4], whA.y, h2v.y);
                    ffma2(d3[m4], whB.x, h2v.x); ffma2(d3[m4], whB.y, h2v.y);
                }
            }
#pragma unroll
            for (int m4 = 0; m4 < 4; m4++) {
                int m = 4 * p + m4;
                float2 p1 = unpack2(a1[m4]);
                float2 q1 = unpack2(d1[m4]);
                z1s[m][j]  = sigap(p1.x + p1.y);                      // rows 0-63: sigmoid
                z1s[m][j2] = fmaf(mAB, tanhap(mSB * (q1.x + q1.y)), mBB);
                if (t) {
                    float2 rmm = rm[m];
                    float2 p2 = unpack2(a2[m4]), p3 = unpack2(a3[m4]);
                    float2 q2 = unpack2(d2[m4]), q3 = unpack2(d3[m4]);
                    float zA = fmaf(rmm.x, p2.x + p2.y,
                                    fmaf(rmm.y, stilA, qA) + p3.x + p3.y);
                    float zB = fmaf(rmm.x, q2.x + q2.y,
                                    fmaf(rmm.y, stilB, qB) + q3.x + q3.y);
                    z2s[m][j]  = sigap(zA);
                    z2s[m][j2] = fmaf(mAB, tanhap(mSB * zB), mBB);
                }
            }
        }
        __syncthreads();

        // ================= Phase2: 8 nodes per thread =================
        if (t) {   // cell2(t-1)
#pragma unroll
            for (int k = 0; k < 8; k++) {
                int n = 2 * k + w;
                float gi = z2s[n][u],        gf = z2s[n][H + u];
                float gg = z2s[n][2 * H + u], go = z2s[n][3 * H + u];
                c2[k] = fmaf(gf, c2[k], gi * gg);
                float h = go * tanhap(c2[k]);
                if (t < SEQ) h2s[n][u] = h;
                else         g_h2[(base + n) * H + u] = h;
            }
        }
        if (t < SEQ) {   // cell1(t) + LN stats
            ull sv[8];
            float hv[8];
#pragma unroll
            for (int k = 0; k < 8; k++) {
                int n = 2 * k + w;
                float gi = z1s[n][u],        gf = z1s[n][H + u];
                float gg = z1s[n][2 * H + u], go = z1s[n][3 * H + u];
                c1[k] = fmaf(gf, c1[k], gi * gg);
                hv[k] = go * tanhap(c1[k]);
                sv[k] = pack2(hv[k], hv[k] * hv[k]);
            }
#pragma unroll
            for (int off = 16; off; off >>= 1)
#pragma unroll
                for (int k = 0; k < 8; k++)
                    fadd2(sv[k], __shfl_xor_sync(0xffffffffu, sv[k], off));
#pragma unroll
            for (int k = 0; k < 8; k++) {
                int n = 2 * k + w;
                float2 s = unpack2(sv[k]);
                float mu = s.x * (1.0f / H);
                float ri = rsqrtf(fmaf(-mu, mu, s.y * (1.0f / H)) + 1e-5f);
                h1s[n][u] = hv[k];
                if (u == 0) rm[n] = make_float2(ri, -mu * ri);
            }
        }
        __syncthreads();
    }
}

// =====================================================================
// GCN stage (unchanged)
// =====================================================================
__global__ void dinv_init_kernel() {
    int i = blockIdx.x * blockDim.x + threadIdx.x;
    if (i < N_NODES) g_dinv[i] = 1.0f;
}
__global__ void deg_acc_kernel(const int* __restrict__ ei, const float* __restrict__ ew) {
    int e = blockIdx.x * blockDim.x + threadIdx.x;
    if (e < NE) atomicAdd(&g_dinv[ei[NE + e]], ew[e]);
}
__global__ void dinv_fin_kernel() {
    int i = blockIdx.x * blockDim.x + threadIdx.x;
    if (i < N_NODES) g_dinv[i] = rsqrtf(g_dinv[i]);
}

__global__ void gcn_pre_kernel(const float* __restrict__ inp, const float* __restrict__ Wg,
                               const float* __restrict__ bprev, int apply_elu)
{
    __shared__ float Ws[H * H];
    __shared__ float rows[8][H];
    int tid = threadIdx.x;
    int m = tid >> 5, u = tid & 31;
    int n = blockIdx.x * 8 + m;
    for (int i = tid; i < H * H; i += 256) Ws[i] = Wg[i];
    float v = inp[n * H + u];
    if (apply_elu) { v += bprev[u]; v = v > 0.f ? v : expm1f(v); }
    rows[m][u] = v;
    __syncthreads();
    float acc = 0.f;
#pragma unroll
    for (int k = 0; k < H; k++) acc = fmaf(rows[m][k], Ws[k * H + u], acc);
    float di = g_dinv[n];
    g_hW[n * H + u]  = acc;
    g_agg[n * H + u] = acc * di * di;
}

__global__ void gcn_scatter_kernel(const int* __restrict__ ei, const float* __restrict__ ew)
{
    int idx = blockIdx.x * blockDim.x + threadIdx.x;
    int e = idx >> 5, u = idx & 31;
    int s = ei[e];
    int d = ei[NE + e];
    float nrm = g_dinv[s] * ew[e] * g_dinv[d];
    atomicAdd(&g_agg[d * H + u], nrm * g_hW[s * H + u]);
}

__global__ void final_kernel(const float* __restrict__ bg2, const float* __restrict__ Wfc,
                             const float* __restrict__ bfc, float* __restrict__ out)
{
    int tid = threadIdx.x;
    int m = tid >> 5, u = tid & 31;
    int n = blockIdx.x * 8 + m;
    float g = g_agg[n * H + u] + bg2[u];
    g = g > 0.f ? g : expm1f(g);
    float s = g;
#pragma unroll
    for (int off = 16; off; off >>= 1) s += __shfl_xor_sync(0xffffffffu, s, off);
    float mean = s * (1.0f / H);
    float h2u = g_h2[n * H + u];
    float p0 = h2u * Wfc[u];
    float p1 = h2u * Wfc[33 + u];
#pragma unroll
    for (int off = 16; off; off >>= 1) {
        p0 += __shfl_xor_sync(0xffffffffu, p0, off);
        p1 += __shfl_xor_sync(0xffffffffu, p1, off);
    }
    if (u == 0) {
        float o0 = p0 + mean * Wfc[32]      + bfc[0];
        float o1 = p1 + mean * Wfc[33 + 32] + bfc[1];
        float mx = fmaxf(o0, o1);
        float lse = mx + logf(expf(o0 - mx) + expf(o1 - mx));
        out[n * 2 + 0] = o0 - lse;
        out[n * 2 + 1] = o1 - lse;
    }
}

// =====================================================================
extern "C" void kernel_launch(void* const* d_in, const int* in_sizes, int n_in,
                              void* d_out, int out_size)
{
    const float* x    = (const float*)d_in[0];
    const float* ew   = (const float*)d_in[1];
    const float* Wih1 = (const float*)d_in[2];
    const float* Whh1 = (const float*)d_in[3];
    const float* bih1 = (const float*)d_in[4];
    const float* bhh1 = (const float*)d_in[5];
    const float* lng  = (const float*)d_in[6];
    const float* lnb  = (const float*)d_in[7];
    const float* Wih2 = (const float*)d_in[8];
    const float* Whh2 = (const float*)d_in[9];
    const float* bih2 = (const float*)d_in[10];
    const float* bhh2 = (const float*)d_in[11];
    const float* Wg1  = (const float*)d_in[12];
    const float* bg1  = (const float*)d_in[13];
    const float* Wg2  = (const float*)d_in[14];
    const float* bg2  = (const float*)d_in[15];
    const float* Wfc  = (const float*)d_in[16];
    const float* bfc  = (const float*)d_in[17];
    const int*   eidx = (const int*)d_in[18];
    float* out = (float*)d_out;

    cudaFuncSetAttribute(lstm_kernel,
                         cudaFuncAttributeMaxDynamicSharedMemorySize, DYN_SMEM);

    // keep lstm_kernel as launch #4 for the fixed-skip ncu capture
    dinv_init_kernel<<<N_NODES / 256, 256>>>();
    deg_acc_kernel<<<NE / 256, 256>>>(eidx, ew);
    dinv_fin_kernel<<<N_NODES / 256, 256>>>();

    lstm_kernel<<<N_NODES / NPB, THREADS, DYN_SMEM>>>(
        x, Wih1, Whh1, bih1, bhh1, lng, lnb, Wih2, Whh2, bih2, bhh2);

    gcn_pre_kernel<<<N_NODES / 8, 256>>>(g_h2, Wg1, bg1, 0);
    gcn_scatter_kernel<<<(NE * 32) / 256, 256>>>(eidx, ew);

    gcn_pre_kernel<<<N_NODES / 8, 256>>>(g_agg, Wg2, bg1, 1);
    gcn_scatter_kernel<<<(NE * 32) / 256, 256>>>(eidx, ew);

    final_kernel<<<N_NODES / 8, 256>>>(bg2, Wfc, bfc, out);
}